// round 17
// baseline (speedup 1.0000x reference)
#include <cuda_runtime.h>
#include <cuda_bf16.h>
#include <cstdint>

// out = (((x+2)*3 - 5)/4)^2 = ((3x+1)/4)^2 ; t = fma(0.75, x, 0.25), out = t*t
// 8192*8192 fp32 = 64M elements, pure HBM streaming (512 MB mandatory traffic).
// Pinned at the GB300 HBM controller ceiling: ~6.35-6.47 TB/s (~80% of spec),
// measured invariant across unroll depth (2/4/8), CTA size (256/512), cache
// hints (.ca/.cg/.lu/.cs), and exact-vs-guarded bodies; persistent grid-stride
// regresses ~5% (reduced chip-wide MLP at loop boundaries). This config had
// the best measured wall time of the session (81.70 us) and the simplest
// shape: unroll-2, 16 regs, 83% occupancy.

__global__ __launch_bounds__(256) void ewise_sq_kernel(
    const float4* __restrict__ in, float4* __restrict__ out, int n4)
{
    int i = blockIdx.x * (blockDim.x * 2) + threadIdx.x;
    int stride = blockDim.x;

    if (i < n4) {
        float4 a = in[i];
        float4 r;
        float t0 = fmaf(0.75f, a.x, 0.25f);
        float t1 = fmaf(0.75f, a.y, 0.25f);
        float t2 = fmaf(0.75f, a.z, 0.25f);
        float t3 = fmaf(0.75f, a.w, 0.25f);
        r.x = t0 * t0; r.y = t1 * t1; r.z = t2 * t2; r.w = t3 * t3;
        out[i] = r;
    }
    int j = i + stride;
    if (j < n4) {
        float4 a = in[j];
        float4 r;
        float t0 = fmaf(0.75f, a.x, 0.25f);
        float t1 = fmaf(0.75f, a.y, 0.25f);
        float t2 = fmaf(0.75f, a.z, 0.25f);
        float t3 = fmaf(0.75f, a.w, 0.25f);
        r.x = t0 * t0; r.y = t1 * t1; r.z = t2 * t2; r.w = t3 * t3;
        out[j] = r;
    }
}

// Scalar tail for element counts not divisible by 4 (not hit for 8192x8192).
__global__ void ewise_sq_scalar_tail(const float* __restrict__ in,
                                     float* __restrict__ out,
                                     int start, int n)
{
    int i = start + blockIdx.x * blockDim.x + threadIdx.x;
    if (i < n) {
        float t = fmaf(0.75f, in[i], 0.25f);
        out[i] = t * t;
    }
}

extern "C" void kernel_launch(void* const* d_in, const int* in_sizes, int n_in,
                              void* d_out, int out_size)
{
    const float* x = (const float*)d_in[0];
    float* y = (float*)d_out;
    int n = in_sizes[0];          // 67108864
    int n4 = n >> 2;              // 16777216 float4

    const int threads = 256;
    const int per_block = threads * 2;                 // 512 float4 per block
    int blocks = (n4 + per_block - 1) / per_block;     // 32768 blocks

    ewise_sq_kernel<<<blocks, threads>>>((const float4*)x, (float4*)y, n4);

    int covered = n4 << 2;
    if (covered < n) {
        int rem = n - covered;
        int tb = (rem + 255) / 256;
        ewise_sq_scalar_tail<<<tb, 256>>>(x, y, covered, n);
    }
}